// round 9
// baseline (speedup 1.0000x reference)
#include <cuda_runtime.h>
#include <cuda_fp16.h>
#include <math.h>

#define DIMV 2048
#define NTR  4096
#define MDEVR 8192
#define TST  500
#define ETA  0.1f
#define NTHREADS 512
#define NW_TRAIN 6
#define NW_DEV   10
#define RING     8

#define S_GRAD_F   1.7179869184e10f   /* 2^34 */
#define INV_SGRAD  5.8207660913e-11f  /* 2^-34 */
#define S_DEV_F    4.294967296e9f     /* 2^32 */
#define INV_SDEV   2.3283064365e-10f  /* 2^-32 */

// Persistent device state (static allocation — no cudaMalloc anywhere).
// g_arrive is never reset: barriers leave it a multiple of gridDim.x.
__device__ unsigned long long g_gradacc[DIMV];
__device__ unsigned long long g_devstep[TST + 1];
__device__ unsigned           g_arrive;
__device__ __half g_xn_h[(size_t)NTR * DIMV];     // 16.8 MB
__device__ __half g_dxn_h[(size_t)MDEVR * DIMV];  // 33.6 MB

#define BAR_TRAIN() asm volatile("bar.sync 1, %0;" :: "n"(NW_TRAIN * 32) : "memory")
#define BAR_DEV()   asm volatile("bar.sync 2, %0;" :: "n"(NW_DEV * 32) : "memory")

__device__ __forceinline__ void grid_barrier_train(unsigned nb, int tid) {
    BAR_TRAIN();
    if (tid == 0) {
        __threadfence();
        unsigned old = atomicAdd(&g_arrive, 1u);
        unsigned target = (old / nb + 1u) * nb;
        while (*((volatile unsigned*)&g_arrive) < target) { }
        __threadfence();
    }
    BAR_TRAIN();
}

__device__ __forceinline__ void grid_barrier_full(unsigned nb) {
    __syncthreads();
    if (threadIdx.x == 0) {
        __threadfence();
        unsigned old = atomicAdd(&g_arrive, 1u);
        unsigned target = (old / nb + 1u) * nb;
        while (*((volatile unsigned*)&g_arrive) < target) { }
        __threadfence();
    }
    __syncthreads();
}

__device__ __forceinline__ float dev_loss_elem(float z, float y) {
    return fmaxf(z, 0.0f) - y * z + log1pf(expf(-fabsf(z)));
}

__device__ __forceinline__ void dot8h(__half2* acc2, const uint4& u, const uint4& th) {
    const __half2* h = (const __half2*)&u;
    const __half2* t = (const __half2*)&th;
    acc2[0] = __hfma2(h[0], t[0], acc2[0]);
    acc2[1] = __hfma2(h[1], t[1], acc2[1]);
    acc2[2] = __hfma2(h[2], t[2], acc2[2]);
    acc2[3] = __hfma2(h[3], t[3], acc2[3]);
}

__device__ __forceinline__ void grad8h(__half2* gj, const uint4& u, __half2 ch2) {
    const __half2* h = (const __half2*)&u;
    gj[0] = __hfma2(ch2, h[0], gj[0]);
    gj[1] = __hfma2(ch2, h[1], gj[1]);
    gj[2] = __hfma2(ch2, h[2], gj[2]);
    gj[3] = __hfma2(ch2, h[3], gj[3]);
}

__device__ __forceinline__ float acc4_to_float(const __half2* a) {
    float2 f0 = __half22float2(a[0]);
    float2 f1 = __half22float2(a[1]);
    float2 f2 = __half22float2(a[2]);
    float2 f3 = __half22float2(a[3]);
    return (f0.x + f0.y) + (f1.x + f1.y) + (f2.x + f2.y) + (f3.x + f3.y);
}

// R contiguous train rows; theta fp16 in smem. z identical on all lanes.
template<int R>
__device__ __forceinline__ void train_chunk(
    int n0, int lane, int t, const __half* s_th, __half2* hacc,
    const float* __restrict__ yn, const float* __restrict__ alphas)
{
    const uint4* xp[R];
#pragma unroll
    for (int r = 0; r < R; r++)
        xp[r] = (const uint4*)(g_xn_h + (size_t)(n0 + r) * DIMV);
    const uint4* tp = (const uint4*)s_th;
    const __half2 hz = __float2half2_rn(0.0f);
    __half2 a[R][4];
#pragma unroll
    for (int r = 0; r < R; r++) { a[r][0]=hz; a[r][1]=hz; a[r][2]=hz; a[r][3]=hz; }
#pragma unroll
    for (int j = 0; j < 8; j++) {
        uint4 th = tp[j*32+lane];
#pragma unroll
        for (int r = 0; r < R; r++) {
            uint4 u = xp[r][j*32+lane];
            dot8h(a[r], u, th);
        }
    }
    float z[R];
#pragma unroll
    for (int r = 0; r < R; r++) z[r] = acc4_to_float(a[r]);
#pragma unroll
    for (int o = 16; o; o >>= 1) {
#pragma unroll
        for (int r = 0; r < R; r++)
            z[r] += __shfl_xor_sync(0xffffffffu, z[r], o);
    }
    __half2 ch[R];
#pragma unroll
    for (int r = 0; r < R; r++) {
        float s = 1.0f / (1.0f + expf(-z[r]));
        float c = alphas[(size_t)t * NTR + (n0 + r)] * (s - yn[n0 + r]);
        ch[r] = __float2half2_rn(c);
    }
#pragma unroll
    for (int j = 0; j < 8; j++) {
#pragma unroll
        for (int r = 0; r < R; r++) {
            uint4 u = xp[r][j*32+lane];         // L1 hits
            grad8h(hacc + j*4, u, ch[r]);
        }
    }
}

// R contiguous dev rows; returns full loss sum, identical on all lanes.
template<int R>
__device__ __forceinline__ float dev_chunk(
    int m0, int lane, const __half* s_th, const float* __restrict__ dyn)
{
    const uint4* xp[R];
#pragma unroll
    for (int r = 0; r < R; r++)
        xp[r] = (const uint4*)(g_dxn_h + (size_t)(m0 + r) * DIMV);
    const uint4* tp = (const uint4*)s_th;
    const __half2 hz = __float2half2_rn(0.0f);
    __half2 a[R][4];
#pragma unroll
    for (int r = 0; r < R; r++) { a[r][0]=hz; a[r][1]=hz; a[r][2]=hz; a[r][3]=hz; }
#pragma unroll
    for (int j = 0; j < 8; j++) {
        uint4 th = tp[j*32+lane];
#pragma unroll
        for (int r = 0; r < R; r++) {
            uint4 u = xp[r][j*32+lane];
            dot8h(a[r], u, th);
        }
    }
    float z[R];
#pragma unroll
    for (int r = 0; r < R; r++) z[r] = acc4_to_float(a[r]);
#pragma unroll
    for (int o = 16; o; o >>= 1) {
#pragma unroll
        for (int r = 0; r < R; r++)
            z[r] += __shfl_xor_sync(0xffffffffu, z[r], o);
    }
    float s = 0.0f;
#pragma unroll
    for (int r = 0; r < R; r++) s += dev_loss_elem(z[r], dyn[m0 + r]);
    return s;
}

// ---------------------------------------------------------------------------
__global__ void __launch_bounds__(NTHREADS, 1)
ak_all(const float* __restrict__ theta0,
       const float* __restrict__ xn,  const float* __restrict__ dxn,
       const float* __restrict__ yn,  const float* __restrict__ dyn,
       const float* __restrict__ alphas,
       float* __restrict__ out, int out_size) {
    extern __shared__ char smc[];
    float*  s_theta = (float*)smc;                                     // 8 KB
    __half* s_ring  = (__half*)(smc + DIMV * 4);                       // 32 KB
    __half* s_grad  = (__half*)(smc + DIMV * 4 + (size_t)RING * DIMV * 2);   // 24 KB
    float*  s_devp  = (float*)(smc + DIMV * 4 + (size_t)RING * DIMV * 2
                               + (size_t)NW_TRAIN * DIMV * 2);          // NW_DEV
    volatile int* s_produced = (volatile int*)(s_devp + NW_DEV);
    volatile int* s_consumed = (volatile int*)(s_devp + NW_DEV + 1);

    const int tid  = threadIdx.x;
    const int lane = tid & 31;
    const int w    = tid >> 5;
    const int cta  = blockIdx.x;
    const int ncta = gridDim.x;

    // ---------------- phase 0: convert + zero state (all 512 threads) ----
    {
        const size_t stride = (size_t)ncta * NTHREADS;
        const size_t gid    = (size_t)cta * NTHREADS + tid;
        const size_t n4 = (size_t)NTR * DIMV / 4;
        const size_t m4 = (size_t)MDEVR * DIMV / 4;
        const float4* s0 = (const float4*)xn;
        const float4* s1 = (const float4*)dxn;
        __half2* d0 = (__half2*)g_xn_h;
        __half2* d1 = (__half2*)g_dxn_h;
        for (size_t i = gid; i < n4; i += stride) {
            float4 v = s0[i];
            d0[2*i+0] = __floats2half2_rn(v.x, v.y);
            d0[2*i+1] = __floats2half2_rn(v.z, v.w);
        }
        for (size_t i = gid; i < m4; i += stride) {
            float4 v = s1[i];
            d1[2*i+0] = __floats2half2_rn(v.x, v.y);
            d1[2*i+1] = __floats2half2_rn(v.z, v.w);
        }
        if (gid < DIMV)    g_gradacc[gid] = 0ull;
        if (gid < TST + 1) g_devstep[gid] = 0ull;
        for (size_t j = TST + 1 + gid; j < (size_t)out_size; j += stride)
            out[j] = 0.0f;
    }
    for (int d = tid; d < DIMV; d += NTHREADS) s_theta[d] = theta0[d];
    if (tid == 0) { *s_produced = 0; *s_consumed = 0; }
    grid_barrier_full((unsigned)ncta);

    const int rb = (int)(((long long)cta * NTR) / ncta);
    const int re = (int)(((long long)(cta + 1) * NTR) / ncta);
    const int mb = (int)(((long long)cta * MDEVR) / ncta);
    const int me = (int)(((long long)(cta + 1) * MDEVR) / ncta);

    if (w < NW_TRAIN) {
        // =================== TRAIN ROLE (critical path) ===================
        const int twb = rb + (int)(((long long)(re - rb) * w) / NW_TRAIN);
        const int twe = rb + (int)(((long long)(re - rb) * (w + 1)) / NW_TRAIN);
        long long prev[11];
#pragma unroll
        for (int i = 0; i < 11; i++) prev[i] = 0ll;
        const __half2 hz = __float2half2_rn(0.0f);

        for (int t = 0; t <= TST; ++t) {
            // ---- produce theta_t fp16 into ring slot t%RING
            while (*s_consumed < t - RING + 1) { }
            {
                __half2* rp = (__half2*)(s_ring + (size_t)(t % RING) * DIMV);
                for (int i = tid; i < DIMV / 2; i += NW_TRAIN * 32)
                    rp[i] = __floats2half2_rn(s_theta[2*i], s_theta[2*i+1]);
            }
            BAR_TRAIN();                    // ring writes drained
            if (tid == 0) *s_produced = t + 1;
            if (t == TST) break;            // slot TST is the final-eval theta

            const __half* s_th = s_ring + (size_t)(t % RING) * DIMV;

            // ---- gradient over this warp's train rows
            __half2 hacc[32];
#pragma unroll
            for (int j = 0; j < 32; j++) hacc[j] = hz;
            {
                int n = twb;
                for (; n + 2 <= twe; n += 2) train_chunk<2>(n, lane, t, s_th, hacc, yn, alphas);
                if (n < twe)                 train_chunk<1>(n, lane, t, s_th, hacc, yn, alphas);
            }
            {
                uint4* gp4 = (uint4*)(s_grad + (size_t)w * DIMV);
#pragma unroll
                for (int j = 0; j < 8; j++) {
                    uint4 u;
                    ((__half2*)&u)[0] = hacc[j*4+0];
                    ((__half2*)&u)[1] = hacc[j*4+1];
                    ((__half2*)&u)[2] = hacc[j*4+2];
                    ((__half2*)&u)[3] = hacc[j*4+3];
                    gp4[j*32+lane] = u;
                }
            }
            BAR_TRAIN();

            // ---- CTA reduce (fixed warp order) + fixed-point atomics
            {
                const __half2* sg2 = (const __half2*)s_grad;
                for (int idx = tid; idx < DIMV / 2; idx += NW_TRAIN * 32) {
                    float2 s = make_float2(0.0f, 0.0f);
#pragma unroll
                    for (int ww = 0; ww < NW_TRAIN; ww++) {
                        float2 f = __half22float2(sg2[ww * (DIMV/2) + idx]);
                        s.x += f.x; s.y += f.y;
                    }
                    atomicAdd(&g_gradacc[2*idx+0], (unsigned long long)llrintf(s.x * S_GRAD_F));
                    atomicAdd(&g_gradacc[2*idx+1], (unsigned long long)llrintf(s.y * S_GRAD_F));
                }
            }

            grid_barrier_train((unsigned)ncta, tid);

            // ---- apply delta to fp32 theta (identical in every CTA)
            {
                const long long* ga = (const long long*)g_gradacc;
                int k = 0;
                for (int d = tid; d < DIMV; d += NW_TRAIN * 32, k++) {
                    long long v = ga[d];
                    float g = (float)(v - prev[k]) * INV_SGRAD;
                    prev[k] = v;
                    s_theta[d] -= ETA * g;
                }
            }
            BAR_TRAIN();                    // theta update visible to producers
        }
    } else {
        // =================== DEV ROLE (off critical path) =================
        const int dw  = w - NW_TRAIN;
        const int dwb = mb + (int)(((long long)(me - mb) * dw) / NW_DEV);
        const int dwe = mb + (int)(((long long)(me - mb) * (dw + 1)) / NW_DEV);

        for (int td = 0; td <= TST; ++td) {
            while (*s_produced < td + 1) { }
            __threadfence_block();
            const __half* s_th = s_ring + (size_t)(td % RING) * DIMV;

            float dsum = 0.0f;
            int m = dwb;
            for (; m + 2 <= dwe; m += 2) dsum += dev_chunk<2>(m, lane, s_th, dyn);
            if (m < dwe)                 dsum += dev_chunk<1>(m, lane, s_th, dyn);
            if (lane == 0) s_devp[dw] = dsum;
            BAR_DEV();                      // all dev warps done with slot td
            if (dw == 0 && lane == 0) {
                float s = 0.0f;
#pragma unroll
                for (int i = 0; i < NW_DEV; i++) s += s_devp[i];
                atomicAdd(&g_devstep[td], (unsigned long long)llrintf(s * S_DEV_F));
                *s_consumed = td + 1;       // release ring slot
            }
        }
    }

    // ---------------- epilogue: all roles converge, then write outputs ----
    __syncthreads();
    grid_barrier_full((unsigned)ncta);
    if (cta == 0) {
        for (int ts = tid; ts < TST; ts += NTHREADS) {
            float L = (float)((long long)g_devstep[ts]) * INV_SDEV * (1.0f / MDEVR);
            if (1 + ts < out_size) out[1 + ts] = L;
        }
        if (tid == 0) {
            float isum = 0.0f;
            for (int t = 1; t <= TST; t++)
                isum += (float)((long long)g_devstep[t]) * INV_SDEV * (1.0f / MDEVR);
            if (out_size > 0) out[0] = isum / (float)TST;
        }
    }
}

// ---------------------------------------------------------------------------
extern "C" void kernel_launch(void* const* d_in, const int* in_sizes, int n_in,
                              void* d_out, int out_size) {
    const float *theta = nullptr, *alphas = nullptr, *xn = nullptr,
                *yn = nullptr, *dxn = nullptr, *dyn = nullptr;
    for (int i = 0; i < n_in; i++) {
        switch (in_sizes[i]) {
            case DIMV:         theta  = (const float*)d_in[i]; break;
            case TST * NTR:    alphas = (const float*)d_in[i]; break;
            case NTR * DIMV:   xn     = (const float*)d_in[i]; break;
            case NTR:          yn     = (const float*)d_in[i]; break;
            case MDEVR * DIMV: dxn    = (const float*)d_in[i]; break;
            case MDEVR:        dyn    = (const float*)d_in[i]; break;
            default: break;
        }
    }
    float* out = (float*)d_out;

    int dev = 0;
    cudaGetDevice(&dev);
    int nsm = 148;
    cudaDeviceGetAttribute(&nsm, cudaDevAttrMultiProcessorCount, dev);
    int ncta = nsm < 1 ? 1 : nsm;

    size_t smem = (size_t)DIMV * 4                 // s_theta fp32
                + (size_t)RING * DIMV * 2          // theta ring fp16
                + (size_t)NW_TRAIN * DIMV * 2      // s_grad
                + (NW_DEV + 2) * sizeof(float);    // s_devp + flags (~64.1 KB)
    cudaFuncSetAttribute(ak_all, cudaFuncAttributeMaxDynamicSharedMemorySize,
                         (int)smem);

    ak_all<<<ncta, NTHREADS, smem>>>(theta, xn, dxn, yn, dyn, alphas,
                                     out, out_size);
}

// round 11
// speedup vs baseline: 1.1027x; 1.1027x over previous
#include <cuda_runtime.h>
#include <cuda_fp16.h>
#include <math.h>

#define DIMV 2048
#define NTR  4096
#define MDEVR 8192
#define TST  500
#define ETA  0.1f
#define NTHREADS 512
#define NWARPS 16

#define S_DEV_F    4.294967296e9f     /* 2^32 */
#define INV_SDEV   2.3283064365e-10f  /* 2^-32 */

// Persistent device state (static allocation — no cudaMalloc anywhere).
// g_arrive is never reset: barriers leave it a multiple of gridDim.x.
__device__ float              g_gradaccf[DIMV];   // f32 running totals
__device__ unsigned long long g_devacc;           // fixed-point running total
__device__ unsigned           g_arrive;
__device__ __half g_xn_h[(size_t)NTR * DIMV];     // 16.8 MB
__device__ __half g_dxn_h[(size_t)MDEVR * DIMV];  // 33.6 MB

// Fast grid barrier: NO gpu-scope __threadfence (avoids CCTL.IVALL L1 flush).
// Callers must have done membar.gl after their global writes/REDs, and must
// read cross-CTA data with .cg/.cv (L2-direct) afterwards.
__device__ __forceinline__ void grid_barrier_fast(unsigned nb) {
    __syncthreads();
    if (threadIdx.x == 0) {
        asm volatile("membar.gl;" ::: "memory");
        unsigned old = atomicAdd(&g_arrive, 1u);
        unsigned target = (old / nb + 1u) * nb;
        while (*((volatile unsigned*)&g_arrive) < target) { }
    }
    __syncthreads();
}

// Full-strength barrier for init/epilogue (rare).
__device__ __forceinline__ void grid_barrier_full(unsigned nb) {
    __syncthreads();
    if (threadIdx.x == 0) {
        __threadfence();
        unsigned old = atomicAdd(&g_arrive, 1u);
        unsigned target = (old / nb + 1u) * nb;
        while (*((volatile unsigned*)&g_arrive) < target) { }
        __threadfence();
    }
    __syncthreads();
}

__device__ __forceinline__ float dev_loss_elem(float z, float y) {
    return fmaxf(z, 0.0f) - y * z + log1pf(expf(-fabsf(z)));
}

__device__ __forceinline__ void dot8h(__half2* acc2, const uint4& u, const uint4& th) {
    const __half2* h = (const __half2*)&u;
    const __half2* t = (const __half2*)&th;
    acc2[0] = __hfma2(h[0], t[0], acc2[0]);
    acc2[1] = __hfma2(h[1], t[1], acc2[1]);
    acc2[2] = __hfma2(h[2], t[2], acc2[2]);
    acc2[3] = __hfma2(h[3], t[3], acc2[3]);
}

__device__ __forceinline__ void grad8h(__half2* gj, const uint4& u, __half2 ch2) {
    const __half2* h = (const __half2*)&u;
    gj[0] = __hfma2(ch2, h[0], gj[0]);
    gj[1] = __hfma2(ch2, h[1], gj[1]);
    gj[2] = __hfma2(ch2, h[2], gj[2]);
    gj[3] = __hfma2(ch2, h[3], gj[3]);
}

__device__ __forceinline__ float acc4_to_float(const __half2* a) {
    float2 f0 = __half22float2(a[0]);
    float2 f1 = __half22float2(a[1]);
    float2 f2 = __half22float2(a[2]);
    float2 f3 = __half22float2(a[3]);
    return (f0.x + f0.y) + (f1.x + f1.y) + (f2.x + f2.y) + (f3.x + f3.y);
}

// R contiguous train rows; theta fp16 in smem. z identical on all lanes.
template<int R>
__device__ __forceinline__ void train_chunk(
    int n0, int lane, int t, const __half* s_th, __half2* hacc,
    const float* __restrict__ yn, const float* __restrict__ alphas)
{
    const uint4* xp[R];
#pragma unroll
    for (int r = 0; r < R; r++)
        xp[r] = (const uint4*)(g_xn_h + (size_t)(n0 + r) * DIMV);
    const uint4* tp = (const uint4*)s_th;
    const __half2 hz = __float2half2_rn(0.0f);
    __half2 a[R][4];
#pragma unroll
    for (int r = 0; r < R; r++) { a[r][0]=hz; a[r][1]=hz; a[r][2]=hz; a[r][3]=hz; }
#pragma unroll
    for (int j = 0; j < 8; j++) {
        uint4 th = tp[j*32+lane];
#pragma unroll
        for (int r = 0; r < R; r++) {
            uint4 u = xp[r][j*32+lane];
            dot8h(a[r], u, th);
        }
    }
    float z[R];
#pragma unroll
    for (int r = 0; r < R; r++) z[r] = acc4_to_float(a[r]);
#pragma unroll
    for (int o = 16; o; o >>= 1) {
#pragma unroll
        for (int r = 0; r < R; r++)
            z[r] += __shfl_xor_sync(0xffffffffu, z[r], o);
    }
    __half2 ch[R];
#pragma unroll
    for (int r = 0; r < R; r++) {
        float s = 1.0f / (1.0f + expf(-z[r]));
        float c = alphas[(size_t)t * NTR + (n0 + r)] * (s - yn[n0 + r]);
        ch[r] = __float2half2_rn(c);
    }
#pragma unroll
    for (int j = 0; j < 8; j++) {
#pragma unroll
        for (int r = 0; r < R; r++) {
            uint4 u = xp[r][j*32+lane];         // L1 hits
            grad8h(hacc + j*4, u, ch[r]);
        }
    }
}

// R contiguous dev rows; returns full loss sum, identical on all lanes.
template<int R>
__device__ __forceinline__ float dev_chunk(
    int m0, int lane, const __half* s_th, const float* __restrict__ dyn)
{
    const uint4* xp[R];
#pragma unroll
    for (int r = 0; r < R; r++)
        xp[r] = (const uint4*)(g_dxn_h + (size_t)(m0 + r) * DIMV);
    const uint4* tp = (const uint4*)s_th;
    const __half2 hz = __float2half2_rn(0.0f);
    __half2 a[R][4];
#pragma unroll
    for (int r = 0; r < R; r++) { a[r][0]=hz; a[r][1]=hz; a[r][2]=hz; a[r][3]=hz; }
#pragma unroll
    for (int j = 0; j < 8; j++) {
        uint4 th = tp[j*32+lane];
#pragma unroll
        for (int r = 0; r < R; r++) {
            uint4 u = xp[r][j*32+lane];
            dot8h(a[r], u, th);
        }
    }
    float z[R];
#pragma unroll
    for (int r = 0; r < R; r++) z[r] = acc4_to_float(a[r]);
#pragma unroll
    for (int o = 16; o; o >>= 1) {
#pragma unroll
        for (int r = 0; r < R; r++)
            z[r] += __shfl_xor_sync(0xffffffffu, z[r], o);
    }
    float s = 0.0f;
#pragma unroll
    for (int r = 0; r < R; r++) s += dev_loss_elem(z[r], dyn[m0 + r]);
    return s;
}

// ---------------------------------------------------------------------------
__global__ void __launch_bounds__(NTHREADS, 1)
ak_all(const float* __restrict__ theta0,
       const float* __restrict__ xn,  const float* __restrict__ dxn,
       const float* __restrict__ yn,  const float* __restrict__ dyn,
       const float* __restrict__ alphas,
       float* __restrict__ out, int out_size) {
    extern __shared__ char smc[];
    float*  s_theta = (float*)smc;                               // 8 KB fp32
    __half* s_th2h  = (__half*)(smc + DIMV * 4);                 // 4 KB fp16
    __half* s_grad  = (__half*)(smc + DIMV * 4 + DIMV * 2);      // 64 KB
    float*  s_dev   = (float*)(smc + DIMV * 4 + DIMV * 2
                               + (size_t)NWARPS * DIMV * 2);     // 16 floats

    const int tid  = threadIdx.x;
    const int lane = tid & 31;
    const int w    = tid >> 5;
    const int cta  = blockIdx.x;
    const int ncta = gridDim.x;

    // ---------------- phase 0: convert + zero running totals --------------
    {
        const size_t stride = (size_t)ncta * NTHREADS;
        const size_t gid    = (size_t)cta * NTHREADS + tid;
        const size_t n4 = (size_t)NTR * DIMV / 4;
        const size_t m4 = (size_t)MDEVR * DIMV / 4;
        const float4* s0 = (const float4*)xn;
        const float4* s1 = (const float4*)dxn;
        __half2* d0 = (__half2*)g_xn_h;
        __half2* d1 = (__half2*)g_dxn_h;
        for (size_t i = gid; i < n4; i += stride) {
            float4 v = s0[i];
            d0[2*i+0] = __floats2half2_rn(v.x, v.y);
            d0[2*i+1] = __floats2half2_rn(v.z, v.w);
        }
        for (size_t i = gid; i < m4; i += stride) {
            float4 v = s1[i];
            d1[2*i+0] = __floats2half2_rn(v.x, v.y);
            d1[2*i+1] = __floats2half2_rn(v.z, v.w);
        }
        if (gid < DIMV)  g_gradaccf[gid] = 0.0f;
        if (gid == DIMV) g_devacc = 0ull;
        for (size_t j = TST + 1 + gid; j < (size_t)out_size; j += stride)
            out[j] = 0.0f;
    }
    for (int d = tid; d < DIMV; d += NTHREADS) s_theta[d] = theta0[d];
    grid_barrier_full((unsigned)ncta);

    const int rb = (int)(((long long)cta * NTR) / ncta);
    const int re = (int)(((long long)(cta + 1) * NTR) / ncta);
    const int mb = (int)(((long long)cta * MDEVR) / ncta);
    const int me = (int)(((long long)(cta + 1) * MDEVR) / ncta);
    const int twb = rb + (int)(((long long)(re - rb) * w) / NWARPS);
    const int twe = rb + (int)(((long long)(re - rb) * (w + 1)) / NWARPS);
    const int dwb = mb + (int)(((long long)(me - mb) * w) / NWARPS);
    const int dwe = mb + (int)(((long long)(me - mb) * (w + 1)) / NWARPS);

    float4 prev = make_float4(0.0f, 0.0f, 0.0f, 0.0f);  // totals for dims tid*4..+3
    long long devprev = 0ll;
    float isum = 0.0f;   // cta0/tid0 only
    const __half2 hz = __float2half2_rn(0.0f);

    for (int t = 0; t < TST; ++t) {
        // ---- refresh fp16 theta in smem
        {
            float4 v = ((const float4*)s_theta)[tid];
            __half2 h0 = __floats2half2_rn(v.x, v.y);
            __half2 h1 = __floats2half2_rn(v.z, v.w);
            uint2 u; u.x = *(unsigned*)&h0; u.y = *(unsigned*)&h1;
            ((uint2*)s_th2h)[tid] = u;
        }
        __syncthreads();

        // ---- train rows (pair -> single)
        __half2 hacc[32];
#pragma unroll
        for (int j = 0; j < 32; j++) hacc[j] = hz;
        {
            int n = twb;
            for (; n + 2 <= twe; n += 2) train_chunk<2>(n, lane, t, s_th2h, hacc, yn, alphas);
            if (n < twe)                 train_chunk<1>(n, lane, t, s_th2h, hacc, yn, alphas);
        }
        {
            uint4* gp4 = (uint4*)(s_grad + (size_t)w * DIMV);
#pragma unroll
            for (int j = 0; j < 8; j++) {
                uint4 u;
                ((__half2*)&u)[0] = hacc[j*4+0];
                ((__half2*)&u)[1] = hacc[j*4+1];
                ((__half2*)&u)[2] = hacc[j*4+2];
                ((__half2*)&u)[3] = hacc[j*4+3];
                gp4[j*32+lane] = u;
            }
        }
        __syncthreads();

        // ---- CTA reduce + f32 REDs FIRST (drain overlaps the dev phase)
        {
            const __half2* sg2 = (const __half2*)s_grad;
#pragma unroll
            for (int i = 0; i < 2; i++) {           // (DIMV/2)/NTHREADS = 2
                int idx = tid + i * NTHREADS;
                float2 s = make_float2(0.0f, 0.0f);
#pragma unroll
                for (int ww = 0; ww < NWARPS; ww++) {
                    float2 f = __half22float2(sg2[ww * (DIMV/2) + idx]);
                    s.x += f.x; s.y += f.y;
                }
                atomicAdd(&g_gradaccf[2*idx+0], s.x);
                atomicAdd(&g_gradaccf[2*idx+1], s.y);
            }
        }

        // ---- dev loss with theta_t (= full_losses[t]); overlaps RED drain
        float dsum = 0.0f;
        {
            int m = dwb;
            for (; m + 2 <= dwe; m += 2) dsum += dev_chunk<2>(m, lane, s_th2h, dyn);
            if (m < dwe)                 dsum += dev_chunk<1>(m, lane, s_th2h, dyn);
        }
        if (lane == 0) s_dev[w] = dsum;
        __syncthreads();
        if (tid == 0) {
            float s = 0.0f;
#pragma unroll
            for (int i = 0; i < NWARPS; i++) s += s_dev[i];
            atomicAdd(&g_devacc, (unsigned long long)llrintf(s * S_DEV_F));
        }
        // release: every thread drains its own REDs (issued long ago -> cheap)
        asm volatile("membar.gl;" ::: "memory");

        grid_barrier_fast((unsigned)ncta);

        // ---- apply delta; L2-direct reads (no L1 staleness, no IVALL needed)
        {
            float4 v = __ldcg(((const float4*)g_gradaccf) + tid);
            float4 g;
            g.x = v.x - prev.x; g.y = v.y - prev.y;
            g.z = v.z - prev.z; g.w = v.w - prev.w;
            prev = v;
            int d = tid * 4;
            s_theta[d+0] -= ETA * g.x;
            s_theta[d+1] -= ETA * g.y;
            s_theta[d+2] -= ETA * g.z;
            s_theta[d+3] -= ETA * g.w;
            if (cta == 0 && tid == 0) {
                long long dv = (long long)__ldcg(&g_devacc);
                float Lt = (float)(dv - devprev) * INV_SDEV * (1.0f / MDEVR);
                devprev = dv;
                if (1 + t < out_size) out[1 + t] = Lt;
                if (t >= 1) isum += Lt;
            }
        }
        __syncthreads();
    }

    // ---- final dev eval at theta_T; finalize scalar loss
    {
        float4 v = ((const float4*)s_theta)[tid];
        __half2 h0 = __floats2half2_rn(v.x, v.y);
        __half2 h1 = __floats2half2_rn(v.z, v.w);
        uint2 u; u.x = *(unsigned*)&h0; u.y = *(unsigned*)&h1;
        ((uint2*)s_th2h)[tid] = u;
    }
    __syncthreads();
    {
        float dsum = 0.0f;
        int m = dwb;
        for (; m + 2 <= dwe; m += 2) dsum += dev_chunk<2>(m, lane, s_th2h, dyn);
        if (m < dwe)                 dsum += dev_chunk<1>(m, lane, s_th2h, dyn);
        if (lane == 0) s_dev[w] = dsum;
        __syncthreads();
        if (tid == 0) {
            float s = 0.0f;
#pragma unroll
            for (int i = 0; i < NWARPS; i++) s += s_dev[i];
            atomicAdd(&g_devacc, (unsigned long long)llrintf(s * S_DEV_F));
        }
        grid_barrier_full((unsigned)ncta);
        if (cta == 0 && tid == 0) {
            long long dv = (long long)g_devacc;
            float LT = (float)(dv - devprev) * INV_SDEV * (1.0f / MDEVR);
            if (out_size > 0) out[0] = (isum + LT) / (float)TST;
        }
    }
}

// ---------------------------------------------------------------------------
extern "C" void kernel_launch(void* const* d_in, const int* in_sizes, int n_in,
                              void* d_out, int out_size) {
    const float *theta = nullptr, *alphas = nullptr, *xn = nullptr,
                *yn = nullptr, *dxn = nullptr, *dyn = nullptr;
    for (int i = 0; i < n_in; i++) {
        switch (in_sizes[i]) {
            case DIMV:         theta  = (const float*)d_in[i]; break;
            case TST * NTR:    alphas = (const float*)d_in[i]; break;
            case NTR * DIMV:   xn     = (const float*)d_in[i]; break;
            case NTR:          yn     = (const float*)d_in[i]; break;
            case MDEVR * DIMV: dxn    = (const float*)d_in[i]; break;
            case MDEVR:        dyn    = (const float*)d_in[i]; break;
            default: break;
        }
    }
    float* out = (float*)d_out;

    int dev = 0;
    cudaGetDevice(&dev);
    int nsm = 0;
    cudaDeviceGetAttribute(&nsm, cudaDevAttrMultiProcessorCount, dev);
    int ncta = nsm;
    if (ncta < 1)   ncta = 148;   // defensive: attribute query failed
    if (ncta > 512) ncta = 512;

    size_t smem = (size_t)DIMV * 4            // s_theta fp32
                + (size_t)DIMV * 2            // s_th2h fp16
                + (size_t)NWARPS * DIMV * 2   // s_grad
                + NWARPS * sizeof(float);     // s_dev   (~76.1 KB)
    cudaFuncSetAttribute(ak_all, cudaFuncAttributeMaxDynamicSharedMemorySize,
                         (int)smem);

    ak_all<<<ncta, NTHREADS, smem>>>(theta, xn, dxn, yn, dyn, alphas,
                                     out, out_size);
}

// round 12
// speedup vs baseline: 1.1873x; 1.0767x over previous
#include <cuda_runtime.h>
#include <cuda_fp16.h>
#include <math.h>

#define DIMV 2048
#define NTR  4096
#define MDEVR 8192
#define TST  500
#define ETA  0.1f
#define NTHREADS 512
#define NWARPS 16

#define S_DEV_F    4.294967296e9f     /* 2^32 */
#define INV_SDEV   2.3283064365e-10f  /* 2^-32 */

// Persistent device state (static allocation — no cudaMalloc anywhere).
// g_arrive is never reset: barriers leave it a multiple of gridDim.x.
__device__ float              g_gradaccf[DIMV];   // f32 running totals
__device__ unsigned long long g_devacc;           // fixed-point running total
__device__ unsigned           g_arrive;
__device__ __half g_xn_h[(size_t)NTR * DIMV];     // 16.8 MB
__device__ __half g_dxn_h[(size_t)MDEVR * DIMV];  // 33.6 MB

// Fast grid barrier: NO gpu-scope __threadfence (no CCTL.IVALL L1 flush).
// Callers must have issued membar.gl (all threads with pending global writes)
// before entering, and must read cross-CTA data with .cg afterwards.
__device__ __forceinline__ void grid_barrier_fast(unsigned nb) {
    __syncthreads();
    if (threadIdx.x == 0) {
        asm volatile("membar.gl;" ::: "memory");
        unsigned old = atomicAdd(&g_arrive, 1u);
        unsigned target = (old / nb + 1u) * nb;
        while (*((volatile unsigned*)&g_arrive) < target) { }
    }
    __syncthreads();
}

// Full-strength barrier for init/epilogue (rare).
__device__ __forceinline__ void grid_barrier_full(unsigned nb) {
    __syncthreads();
    if (threadIdx.x == 0) {
        __threadfence();
        unsigned old = atomicAdd(&g_arrive, 1u);
        unsigned target = (old / nb + 1u) * nb;
        while (*((volatile unsigned*)&g_arrive) < target) { }
        __threadfence();
    }
    __syncthreads();
}

__device__ __forceinline__ float dev_loss_elem(float z, float y) {
    return fmaxf(z, 0.0f) - y * z + log1pf(expf(-fabsf(z)));
}

__device__ __forceinline__ void dot8h(__half2* acc2, const uint4& u, const uint4& th) {
    const __half2* h = (const __half2*)&u;
    const __half2* t = (const __half2*)&th;
    acc2[0] = __hfma2(h[0], t[0], acc2[0]);
    acc2[1] = __hfma2(h[1], t[1], acc2[1]);
    acc2[2] = __hfma2(h[2], t[2], acc2[2]);
    acc2[3] = __hfma2(h[3], t[3], acc2[3]);
}

__device__ __forceinline__ void grad8h(__half2* gj, const uint4& u, __half2 ch2) {
    const __half2* h = (const __half2*)&u;
    gj[0] = __hfma2(ch2, h[0], gj[0]);
    gj[1] = __hfma2(ch2, h[1], gj[1]);
    gj[2] = __hfma2(ch2, h[2], gj[2]);
    gj[3] = __hfma2(ch2, h[3], gj[3]);
}

__device__ __forceinline__ float acc4_to_float(const __half2* a) {
    float2 f0 = __half22float2(a[0]);
    float2 f1 = __half22float2(a[1]);
    float2 f2 = __half22float2(a[2]);
    float2 f3 = __half22float2(a[3]);
    return (f0.x + f0.y) + (f1.x + f1.y) + (f2.x + f2.y) + (f3.x + f3.y);
}

// R contiguous train rows; theta fp16 in smem. z identical on all lanes.
template<int R>
__device__ __forceinline__ void train_chunk(
    int n0, int lane, int t, const __half* s_th, __half2* hacc,
    const float* __restrict__ yn, const float* __restrict__ alphas)
{
    const uint4* xp[R];
#pragma unroll
    for (int r = 0; r < R; r++)
        xp[r] = (const uint4*)(g_xn_h + (size_t)(n0 + r) * DIMV);
    const uint4* tp = (const uint4*)s_th;
    const __half2 hz = __float2half2_rn(0.0f);
    __half2 a[R][4];
#pragma unroll
    for (int r = 0; r < R; r++) { a[r][0]=hz; a[r][1]=hz; a[r][2]=hz; a[r][3]=hz; }
#pragma unroll
    for (int j = 0; j < 8; j++) {
        uint4 th = tp[j*32+lane];
#pragma unroll
        for (int r = 0; r < R; r++) {
            uint4 u = xp[r][j*32+lane];
            dot8h(a[r], u, th);
        }
    }
    float z[R];
#pragma unroll
    for (int r = 0; r < R; r++) z[r] = acc4_to_float(a[r]);
#pragma unroll
    for (int o = 16; o; o >>= 1) {
#pragma unroll
        for (int r = 0; r < R; r++)
            z[r] += __shfl_xor_sync(0xffffffffu, z[r], o);
    }
    __half2 ch[R];
#pragma unroll
    for (int r = 0; r < R; r++) {
        float s = 1.0f / (1.0f + expf(-z[r]));
        float c = alphas[(size_t)t * NTR + (n0 + r)] * (s - yn[n0 + r]);
        ch[r] = __float2half2_rn(c);
    }
#pragma unroll
    for (int j = 0; j < 8; j++) {
#pragma unroll
        for (int r = 0; r < R; r++) {
            uint4 u = xp[r][j*32+lane];         // L1 hits
            grad8h(hacc + j*4, u, ch[r]);
        }
    }
}

// R contiguous dev rows; returns full loss sum, identical on all lanes.
template<int R>
__device__ __forceinline__ float dev_chunk(
    int m0, int lane, const __half* s_th, const float* __restrict__ dyn)
{
    const uint4* xp[R];
#pragma unroll
    for (int r = 0; r < R; r++)
        xp[r] = (const uint4*)(g_dxn_h + (size_t)(m0 + r) * DIMV);
    const uint4* tp = (const uint4*)s_th;
    const __half2 hz = __float2half2_rn(0.0f);
    __half2 a[R][4];
#pragma unroll
    for (int r = 0; r < R; r++) { a[r][0]=hz; a[r][1]=hz; a[r][2]=hz; a[r][3]=hz; }
#pragma unroll
    for (int j = 0; j < 8; j++) {
        uint4 th = tp[j*32+lane];
#pragma unroll
        for (int r = 0; r < R; r++) {
            uint4 u = xp[r][j*32+lane];
            dot8h(a[r], u, th);
        }
    }
    float z[R];
#pragma unroll
    for (int r = 0; r < R; r++) z[r] = acc4_to_float(a[r]);
#pragma unroll
    for (int o = 16; o; o >>= 1) {
#pragma unroll
        for (int r = 0; r < R; r++)
            z[r] += __shfl_xor_sync(0xffffffffu, z[r], o);
    }
    float s = 0.0f;
#pragma unroll
    for (int r = 0; r < R; r++) s += dev_loss_elem(z[r], dyn[m0 + r]);
    return s;
}

// ---------------------------------------------------------------------------
__global__ void __launch_bounds__(NTHREADS, 1)
ak_all(const float* __restrict__ theta0,
       const float* __restrict__ xn,  const float* __restrict__ dxn,
       const float* __restrict__ yn,  const float* __restrict__ dyn,
       const float* __restrict__ alphas,
       float* __restrict__ out, int out_size) {
    extern __shared__ char smc[];
    __half* s_th2h = (__half*)smc;                               // 4 KB fp16
    __half* s_grad = (__half*)(smc + DIMV * 2);                  // 64 KB
    float*  s_dev  = (float*)(smc + DIMV * 2
                              + (size_t)NWARPS * DIMV * 2);      // 16 floats

    const int tid  = threadIdx.x;
    const int lane = tid & 31;
    const int w    = tid >> 5;
    const int cta  = blockIdx.x;
    const int ncta = gridDim.x;

    // ---------------- phase 0: convert + zero running totals --------------
    {
        const size_t stride = (size_t)ncta * NTHREADS;
        const size_t gid    = (size_t)cta * NTHREADS + tid;
        const size_t n4 = (size_t)NTR * DIMV / 4;
        const size_t m4 = (size_t)MDEVR * DIMV / 4;
        const float4* s0 = (const float4*)xn;
        const float4* s1 = (const float4*)dxn;
        __half2* d0 = (__half2*)g_xn_h;
        __half2* d1 = (__half2*)g_dxn_h;
        for (size_t i = gid; i < n4; i += stride) {
            float4 v = s0[i];
            d0[2*i+0] = __floats2half2_rn(v.x, v.y);
            d0[2*i+1] = __floats2half2_rn(v.z, v.w);
        }
        for (size_t i = gid; i < m4; i += stride) {
            float4 v = s1[i];
            d1[2*i+0] = __floats2half2_rn(v.x, v.y);
            d1[2*i+1] = __floats2half2_rn(v.z, v.w);
        }
        if (gid < DIMV)  g_gradaccf[gid] = 0.0f;
        if (gid == DIMV) g_devacc = 0ull;
        for (size_t j = TST + 1 + gid; j < (size_t)out_size; j += stride)
            out[j] = 0.0f;
    }
    // theta fp32 -> per-thread registers (dims 4*tid .. 4*tid+3) + fp16 smem
    float4 thf = ((const float4*)theta0)[tid];
    {
        __half2 h0 = __floats2half2_rn(thf.x, thf.y);
        __half2 h1 = __floats2half2_rn(thf.z, thf.w);
        uint2 u; u.x = *(unsigned*)&h0; u.y = *(unsigned*)&h1;
        ((uint2*)s_th2h)[tid] = u;
    }
    grid_barrier_full((unsigned)ncta);

    // CTA row ranges
    const int rb = (int)(((long long)cta * NTR) / ncta);
    const int re = (int)(((long long)(cta + 1) * NTR) / ncta);
    const int mb = (int)(((long long)cta * MDEVR) / ncta);
    const int me = (int)(((long long)(cta + 1) * MDEVR) / ncta);
    const int Tr = re - rb, Dr = me - mb;

    // Weighted unified split: train row = 3 units, dev row = 2 units.
    // Warp w owns unit range [U*w/16, U*(w+1)/16); rows rounded to edges.
    const int U  = 3 * Tr + 2 * Dr;
    const int lo = (int)(((long long)U * w) / NWARPS);
    const int hi = (int)(((long long)U * (w + 1)) / NWARPS);
    int ta = (lo + 2) / 3; if (ta > Tr) ta = Tr;
    int tb = (hi + 2) / 3; if (tb > Tr) tb = Tr;
    int loD = lo - 3 * Tr; if (loD < 0) loD = 0;
    int hiD = hi - 3 * Tr; if (hiD < 0) hiD = 0;
    int da = (loD + 1) / 2; if (da > Dr) da = Dr;
    int db = (hiD + 1) / 2; if (db > Dr) db = Dr;
    const int twb = rb + ta, twe = rb + tb;
    const int dwb = mb + da, dwe = mb + db;
    // even dev-only split for the final evaluation
    const int dfb = mb + (int)(((long long)Dr * w) / NWARPS);
    const int dfe = mb + (int)(((long long)Dr * (w + 1)) / NWARPS);

    float4 prev = make_float4(0.0f, 0.0f, 0.0f, 0.0f);
    long long devprev = 0ll;
    float isum = 0.0f;   // cta0/tid0 only
    const __half2 hz = __float2half2_rn(0.0f);

    for (int t = 0; t < TST; ++t) {
        // ---- unified work region: this warp's train rows, then dev rows
        __half2 hacc[32];
#pragma unroll
        for (int j = 0; j < 32; j++) hacc[j] = hz;
        {
            int n = twb;
            for (; n + 2 <= twe; n += 2) train_chunk<2>(n, lane, t, s_th2h, hacc, yn, alphas);
            if (n < twe)                 train_chunk<1>(n, lane, t, s_th2h, hacc, yn, alphas);
        }
        {   // per-warp grad partial -> smem (zeros if warp had no train rows)
            uint4* gp4 = (uint4*)(s_grad + (size_t)w * DIMV);
#pragma unroll
            for (int j = 0; j < 8; j++) {
                uint4 u;
                ((__half2*)&u)[0] = hacc[j*4+0];
                ((__half2*)&u)[1] = hacc[j*4+1];
                ((__half2*)&u)[2] = hacc[j*4+2];
                ((__half2*)&u)[3] = hacc[j*4+3];
                gp4[j*32+lane] = u;
            }
        }
        float dsum = 0.0f;
        {
            int m = dwb;
            for (; m + 2 <= dwe; m += 2) dsum += dev_chunk<2>(m, lane, s_th2h, dyn);
            if (m < dwe)                 dsum += dev_chunk<1>(m, lane, s_th2h, dyn);
        }
        if (lane == 0) s_dev[w] = dsum;
        __syncthreads();                              // sync A

        // ---- CTA reduce + f32 REDs + dev atomic
        {
            const __half2* sg2 = (const __half2*)s_grad;
#pragma unroll
            for (int i = 0; i < 2; i++) {             // (DIMV/2)/NTHREADS = 2
                int idx = tid + i * NTHREADS;
                float2 s = make_float2(0.0f, 0.0f);
#pragma unroll
                for (int ww = 0; ww < NWARPS; ww++) {
                    float2 f = __half22float2(sg2[ww * (DIMV/2) + idx]);
                    s.x += f.x; s.y += f.y;
                }
                atomicAdd(&g_gradaccf[2*idx+0], s.x);
                atomicAdd(&g_gradaccf[2*idx+1], s.y);
            }
        }
        if (tid == 0) {
            float s = 0.0f;
#pragma unroll
            for (int i = 0; i < NWARPS; i++) s += s_dev[i];
            atomicAdd(&g_devacc, (unsigned long long)llrintf(s * S_DEV_F));
        }
        asm volatile("membar.gl;" ::: "memory");      // drain own REDs

        grid_barrier_fast((unsigned)ncta);            // sync B + arrive/poll

        // ---- apply delta directly in registers; refresh fp16 smem theta
        {
            float4 v = __ldcg(((const float4*)g_gradaccf) + tid);
            thf.x -= ETA * (v.x - prev.x);
            thf.y -= ETA * (v.y - prev.y);
            thf.z -= ETA * (v.z - prev.z);
            thf.w -= ETA * (v.w - prev.w);
            prev = v;
            __half2 h0 = __floats2half2_rn(thf.x, thf.y);
            __half2 h1 = __floats2half2_rn(thf.z, thf.w);
            uint2 u; u.x = *(unsigned*)&h0; u.y = *(unsigned*)&h1;
            ((uint2*)s_th2h)[tid] = u;
            if (cta == 0 && tid == 0) {
                long long dv = (long long)__ldcg(&g_devacc);
                float Lt = (float)(dv - devprev) * INV_SDEV * (1.0f / MDEVR);
                devprev = dv;
                if (1 + t < out_size) out[1 + t] = Lt;
                if (t >= 1) isum += Lt;
            }
        }
        __syncthreads();                              // sync C
    }

    // ---- final dev eval at theta_T (s_th2h is current); finalize loss
    {
        float dsum = 0.0f;
        int m = dfb;
        for (; m + 2 <= dfe; m += 2) dsum += dev_chunk<2>(m, lane, s_th2h, dyn);
        if (m < dfe)                 dsum += dev_chunk<1>(m, lane, s_th2h, dyn);
        if (lane == 0) s_dev[w] = dsum;
        __syncthreads();
        if (tid == 0) {
            float s = 0.0f;
#pragma unroll
            for (int i = 0; i < NWARPS; i++) s += s_dev[i];
            atomicAdd(&g_devacc, (unsigned long long)llrintf(s * S_DEV_F));
        }
        grid_barrier_full((unsigned)ncta);
        if (cta == 0 && tid == 0) {
            long long dv = (long long)g_devacc;
            float LT = (float)(dv - devprev) * INV_SDEV * (1.0f / MDEVR);
            if (out_size > 0) out[0] = (isum + LT) / (float)TST;
        }
    }
}

// ---------------------------------------------------------------------------
extern "C" void kernel_launch(void* const* d_in, const int* in_sizes, int n_in,
                              void* d_out, int out_size) {
    const float *theta = nullptr, *alphas = nullptr, *xn = nullptr,
                *yn = nullptr, *dxn = nullptr, *dyn = nullptr;
    for (int i = 0; i < n_in; i++) {
        switch (in_sizes[i]) {
            case DIMV:         theta  = (const float*)d_in[i]; break;
            case TST * NTR:    alphas = (const float*)d_in[i]; break;
            case NTR * DIMV:   xn     = (const float*)d_in[i]; break;
            case NTR:          yn     = (const float*)d_in[i]; break;
            case MDEVR * DIMV: dxn    = (const float*)d_in[i]; break;
            case MDEVR:        dyn    = (const float*)d_in[i]; break;
            default: break;
        }
    }
    float* out = (float*)d_out;

    int dev = 0;
    cudaGetDevice(&dev);
    int nsm = 0;
    cudaDeviceGetAttribute(&nsm, cudaDevAttrMultiProcessorCount, dev);
    int ncta = nsm;
    if (ncta < 1)   ncta = 148;
    if (ncta > 512) ncta = 512;

    size_t smem = (size_t)DIMV * 2            // s_th2h fp16
                + (size_t)NWARPS * DIMV * 2   // s_grad
                + NWARPS * sizeof(float);     // s_dev   (~68.1 KB)
    cudaFuncSetAttribute(ak_all, cudaFuncAttributeMaxDynamicSharedMemorySize,
                         (int)smem);

    ak_all<<<ncta, NTHREADS, smem>>>(theta, xn, dxn, yn, dyn, alphas,
                                     out, out_size);
}

// round 13
// speedup vs baseline: 1.2008x; 1.0113x over previous
#include <cuda_runtime.h>
#include <cuda_fp16.h>
#include <math.h>

#define DIMV 2048
#define NTR  4096
#define MDEVR 8192
#define TST  500
#define ETA  0.1f
#define NTHREADS 512
#define NWARPS 16

#define S_DEV_F    4.294967296e9f     /* 2^32 */
#define INV_SDEV   2.3283064365e-10f  /* 2^-32 */

// Persistent device state (static allocation — no cudaMalloc anywhere).
// g_arrive is never reset: barriers leave it a multiple of gridDim.x.
__device__ float              g_gradaccf[DIMV];   // f32 running totals
__device__ unsigned long long g_devacc;           // fixed-point running total
__device__ unsigned           g_arrive;
__device__ __half       g_xn_h[(size_t)NTR * DIMV];      // 16.8 MB fp16 train
__device__ signed char  g_dxn_q[(size_t)MDEVR * DIMV];   // 16.8 MB int8 dev
__device__ float        g_sx[MDEVR];                     // per-row dev scales

// Fast grid barrier: NO gpu-scope __threadfence (no CCTL.IVALL L1 flush).
__device__ __forceinline__ void grid_barrier_fast(unsigned nb) {
    __syncthreads();
    if (threadIdx.x == 0) {
        asm volatile("membar.gl;" ::: "memory");
        unsigned old = atomicAdd(&g_arrive, 1u);
        unsigned target = (old / nb + 1u) * nb;
        while (*((volatile unsigned*)&g_arrive) < target) { }
    }
    __syncthreads();
}

__device__ __forceinline__ void grid_barrier_full(unsigned nb) {
    __syncthreads();
    if (threadIdx.x == 0) {
        __threadfence();
        unsigned old = atomicAdd(&g_arrive, 1u);
        unsigned target = (old / nb + 1u) * nb;
        while (*((volatile unsigned*)&g_arrive) < target) { }
        __threadfence();
    }
    __syncthreads();
}

__device__ __forceinline__ float dev_loss_elem(float z, float y) {
    return fmaxf(z, 0.0f) - y * z + log1pf(expf(-fabsf(z)));
}

__device__ __forceinline__ void dot8h(__half2* acc2, const uint4& u, const uint4& th) {
    const __half2* h = (const __half2*)&u;
    const __half2* t = (const __half2*)&th;
    acc2[0] = __hfma2(h[0], t[0], acc2[0]);
    acc2[1] = __hfma2(h[1], t[1], acc2[1]);
    acc2[2] = __hfma2(h[2], t[2], acc2[2]);
    acc2[3] = __hfma2(h[3], t[3], acc2[3]);
}

__device__ __forceinline__ void grad8h(__half2* gj, const uint4& u, __half2 ch2) {
    const __half2* h = (const __half2*)&u;
    gj[0] = __hfma2(ch2, h[0], gj[0]);
    gj[1] = __hfma2(ch2, h[1], gj[1]);
    gj[2] = __hfma2(ch2, h[2], gj[2]);
    gj[3] = __hfma2(ch2, h[3], gj[3]);
}

__device__ __forceinline__ float acc4_to_float(const __half2* a) {
    float2 f0 = __half22float2(a[0]);
    float2 f1 = __half22float2(a[1]);
    float2 f2 = __half22float2(a[2]);
    float2 f3 = __half22float2(a[3]);
    return (f0.x + f0.y) + (f1.x + f1.y) + (f2.x + f2.y) + (f3.x + f3.y);
}

// R contiguous train rows; theta fp16 in smem. z identical on all lanes.
template<int R>
__device__ __forceinline__ void train_chunk(
    int n0, int lane, int t, const __half* s_th, __half2* hacc,
    const float* __restrict__ yn, const float* __restrict__ alphas)
{
    const uint4* xp[R];
#pragma unroll
    for (int r = 0; r < R; r++)
        xp[r] = (const uint4*)(g_xn_h + (size_t)(n0 + r) * DIMV);
    const uint4* tp = (const uint4*)s_th;
    const __half2 hz = __float2half2_rn(0.0f);
    __half2 a[R][4];
#pragma unroll
    for (int r = 0; r < R; r++) { a[r][0]=hz; a[r][1]=hz; a[r][2]=hz; a[r][3]=hz; }
#pragma unroll
    for (int j = 0; j < 8; j++) {
        uint4 th = tp[j*32+lane];
#pragma unroll
        for (int r = 0; r < R; r++) {
            uint4 u = xp[r][j*32+lane];
            dot8h(a[r], u, th);
        }
    }
    float z[R];
#pragma unroll
    for (int r = 0; r < R; r++) z[r] = acc4_to_float(a[r]);
#pragma unroll
    for (int o = 16; o; o >>= 1) {
#pragma unroll
        for (int r = 0; r < R; r++)
            z[r] += __shfl_xor_sync(0xffffffffu, z[r], o);
    }
    __half2 ch[R];
#pragma unroll
    for (int r = 0; r < R; r++) {
        float s = 1.0f / (1.0f + expf(-z[r]));
        float c = alphas[(size_t)t * NTR + (n0 + r)] * (s - yn[n0 + r]);
        ch[r] = __float2half2_rn(c);
    }
#pragma unroll
    for (int j = 0; j < 8; j++) {
#pragma unroll
        for (int r = 0; r < R; r++) {
            uint4 u = xp[r][j*32+lane];         // L1 hits
            grad8h(hacc + j*4, u, ch[r]);
        }
    }
}

// R contiguous dev rows, int8 path: exact dp4a int32 dot; z = sx*sth*acc.
// Returns full loss sum of the R rows, identical on all lanes.
template<int R>
__device__ __forceinline__ float dev_chunk_q(
    int m0, int lane, const signed char* s_thq, float sth,
    const float* __restrict__ dyn)
{
    const uint4* xp[R];
#pragma unroll
    for (int r = 0; r < R; r++)
        xp[r] = (const uint4*)(g_dxn_q + (size_t)(m0 + r) * DIMV);
    const uint4* tp = (const uint4*)s_thq;
    int acc[R];
#pragma unroll
    for (int r = 0; r < R; r++) acc[r] = 0;
#pragma unroll
    for (int j = 0; j < 4; j++) {                 // 4 uint4 = 64 int8 / thread
        uint4 tq = tp[j*32+lane];
#pragma unroll
        for (int r = 0; r < R; r++) {
            uint4 u = xp[r][j*32+lane];
            acc[r] = __dp4a((int)u.x, (int)tq.x, acc[r]);
            acc[r] = __dp4a((int)u.y, (int)tq.y, acc[r]);
            acc[r] = __dp4a((int)u.z, (int)tq.z, acc[r]);
            acc[r] = __dp4a((int)u.w, (int)tq.w, acc[r]);
        }
    }
#pragma unroll
    for (int o = 16; o; o >>= 1) {
#pragma unroll
        for (int r = 0; r < R; r++)
            acc[r] += __shfl_xor_sync(0xffffffffu, acc[r], o);
    }
    float s = 0.0f;
#pragma unroll
    for (int r = 0; r < R; r++) {
        float z = g_sx[m0 + r] * sth * (float)acc[r];
        s += dev_loss_elem(z, dyn[m0 + r]);
    }
    return s;
}

__device__ __forceinline__ signed char quant8(float v, float inv) {
    float q = fminf(fmaxf(v * inv, -127.0f), 127.0f);
    return (signed char)__float2int_rn(q);
}

// ---------------------------------------------------------------------------
__global__ void __launch_bounds__(NTHREADS, 1)
ak_all(const float* __restrict__ theta0,
       const float* __restrict__ xn,  const float* __restrict__ dxn,
       const float* __restrict__ yn,  const float* __restrict__ dyn,
       const float* __restrict__ alphas,
       float* __restrict__ out, int out_size) {
    extern __shared__ char smc[];
    __half*      s_th2h = (__half*)smc;                          // 4 KB fp16
    signed char* s_thq  = (signed char*)(smc + DIMV * 2);        // 2 KB int8
    __half*      s_grad = (__half*)(smc + DIMV * 2 + DIMV);      // 64 KB
    float*       s_dev  = (float*)(smc + DIMV * 2 + DIMV
                                   + (size_t)NWARPS * DIMV * 2); // 16 floats
    float*       s_max  = s_dev + NWARPS;                        // 16 floats

    const int tid  = threadIdx.x;
    const int lane = tid & 31;
    const int w    = tid >> 5;
    const int cta  = blockIdx.x;
    const int ncta = gridDim.x;

    // ---------------- phase 0: convert train fp16 + quantize dev int8 ----
    {
        const size_t stride = (size_t)ncta * NTHREADS;
        const size_t gid    = (size_t)cta * NTHREADS + tid;
        const size_t n4 = (size_t)NTR * DIMV / 4;
        const float4* s0 = (const float4*)xn;
        __half2* d0 = (__half2*)g_xn_h;
        for (size_t i = gid; i < n4; i += stride) {
            float4 v = s0[i];
            d0[2*i+0] = __floats2half2_rn(v.x, v.y);
            d0[2*i+1] = __floats2half2_rn(v.z, v.w);
        }
        // dev: one warp per row — rowmax then quantize (2nd read hits L1)
        const int gwp = cta * NWARPS + w;
        const int nwp = ncta * NWARPS;
        for (int row = gwp; row < MDEVR; row += nwp) {
            const float4* xr = (const float4*)(dxn + (size_t)row * DIMV);
            float mx = 0.0f;
            for (int i = lane; i < DIMV / 4; i += 32) {
                float4 v = xr[i];
                mx = fmaxf(mx, fmaxf(fmaxf(fabsf(v.x), fabsf(v.y)),
                                     fmaxf(fabsf(v.z), fabsf(v.w))));
            }
#pragma unroll
            for (int o = 16; o; o >>= 1)
                mx = fmaxf(mx, __shfl_xor_sync(0xffffffffu, mx, o));
            float inv = (mx > 0.0f) ? 127.0f / mx : 0.0f;
            if (lane == 0) g_sx[row] = (mx > 0.0f) ? mx * (1.0f / 127.0f) : 0.0f;
            char4* dq = (char4*)(g_dxn_q + (size_t)row * DIMV);
            for (int i = lane; i < DIMV / 4; i += 32) {
                float4 v = xr[i];
                char4 q;
                q.x = quant8(v.x, inv); q.y = quant8(v.y, inv);
                q.z = quant8(v.z, inv); q.w = quant8(v.w, inv);
                dq[i] = q;
            }
        }
        if (gid < DIMV)  g_gradaccf[gid] = 0.0f;
        if (gid == DIMV) g_devacc = 0ull;
        for (size_t j = TST + 1 + gid; j < (size_t)out_size; j += stride)
            out[j] = 0.0f;
    }
    // theta fp32 -> registers (dims 4*tid..+3), publish fp16 + warp max
    float4 thf = ((const float4*)theta0)[tid];
    {
        __half2 h0 = __floats2half2_rn(thf.x, thf.y);
        __half2 h1 = __floats2half2_rn(thf.z, thf.w);
        uint2 u; u.x = *(unsigned*)&h0; u.y = *(unsigned*)&h1;
        ((uint2*)s_th2h)[tid] = u;
        float lm = fmaxf(fmaxf(fabsf(thf.x), fabsf(thf.y)),
                         fmaxf(fabsf(thf.z), fabsf(thf.w)));
#pragma unroll
        for (int o = 16; o; o >>= 1)
            lm = fmaxf(lm, __shfl_xor_sync(0xffffffffu, lm, o));
        if (lane == 0) s_max[w] = lm;
    }
    grid_barrier_full((unsigned)ncta);
    float sth;
    {   // quantize theta int8 (identical in every CTA -> deterministic)
        float gmax = s_max[0];
#pragma unroll
        for (int i = 1; i < NWARPS; i++) gmax = fmaxf(gmax, s_max[i]);
        sth = gmax * (1.0f / 127.0f);
        float tinv = (gmax > 0.0f) ? 127.0f / gmax : 0.0f;
        char4 tq;
        tq.x = quant8(thf.x, tinv); tq.y = quant8(thf.y, tinv);
        tq.z = quant8(thf.z, tinv); tq.w = quant8(thf.w, tinv);
        ((char4*)s_thq)[tid] = tq;
    }
    __syncthreads();

    // CTA row ranges
    const int rb = (int)(((long long)cta * NTR) / ncta);
    const int re = (int)(((long long)(cta + 1) * NTR) / ncta);
    const int mb = (int)(((long long)cta * MDEVR) / ncta);
    const int me = (int)(((long long)(cta + 1) * MDEVR) / ncta);
    const int Tr = re - rb, Dr = me - mb;

    // Weighted unified split: train row = 4 units, dev row = 1 unit.
    const int U  = 4 * Tr + Dr;
    const int lo = (int)(((long long)U * w) / NWARPS);
    const int hi = (int)(((long long)U * (w + 1)) / NWARPS);
    int ta = (lo + 3) >> 2; if (ta > Tr) ta = Tr;
    int tb = (hi + 3) >> 2; if (tb > Tr) tb = Tr;
    int da = lo - 4 * Tr; if (da < 0) da = 0;
    int db = hi - 4 * Tr; if (db < 0) db = 0; if (db > Dr) db = Dr;
    const int twb = rb + ta, twe = rb + tb;
    const int dwb = mb + da, dwe = mb + db;
    // even dev-only split for the final evaluation
    const int dfb = mb + (int)(((long long)Dr * w) / NWARPS);
    const int dfe = mb + (int)(((long long)Dr * (w + 1)) / NWARPS);

    float4 prev = make_float4(0.0f, 0.0f, 0.0f, 0.0f);
    long long devprev = 0ll;
    float isum = 0.0f;   // cta0/tid0 only
    const __half2 hz = __float2half2_rn(0.0f);

    for (int t = 0; t < TST; ++t) {
        // ---- unified work region: train rows then dev rows (this warp)
        __half2 hacc[32];
#pragma unroll
        for (int j = 0; j < 32; j++) hacc[j] = hz;
        {
            int n = twb;
            for (; n + 2 <= twe; n += 2) train_chunk<2>(n, lane, t, s_th2h, hacc, yn, alphas);
            if (n < twe)                 train_chunk<1>(n, lane, t, s_th2h, hacc, yn, alphas);
        }
        {
            uint4* gp4 = (uint4*)(s_grad + (size_t)w * DIMV);
#pragma unroll
            for (int j = 0; j < 8; j++) {
                uint4 u;
                ((__half2*)&u)[0] = hacc[j*4+0];
                ((__half2*)&u)[1] = hacc[j*4+1];
                ((__half2*)&u)[2] = hacc[j*4+2];
                ((__half2*)&u)[3] = hacc[j*4+3];
                gp4[j*32+lane] = u;
            }
        }
        float dsum = 0.0f;
        {
            int m = dwb;
            for (; m + 2 <= dwe; m += 2) dsum += dev_chunk_q<2>(m, lane, s_thq, sth, dyn);
            if (m < dwe)                 dsum += dev_chunk_q<1>(m, lane, s_thq, sth, dyn);
        }
        if (lane == 0) s_dev[w] = dsum;
        __syncthreads();                              // sync A

        // ---- CTA reduce + f32 REDs + dev atomic
        {
            const __half2* sg2 = (const __half2*)s_grad;
#pragma unroll
            for (int i = 0; i < 2; i++) {             // (DIMV/2)/NTHREADS = 2
                int idx = tid + i * NTHREADS;
                float2 s = make_float2(0.0f, 0.0f);
#pragma unroll
                for (int ww = 0; ww < NWARPS; ww++) {
                    float2 f = __half22float2(sg2[ww * (DIMV/2) + idx]);
                    s.x += f.x; s.y += f.y;
                }
                atomicAdd(&g_gradaccf[2*idx+0], s.x);
                atomicAdd(&g_gradaccf[2*idx+1], s.y);
            }
        }
        if (tid == 0) {
            float s = 0.0f;
#pragma unroll
            for (int i = 0; i < NWARPS; i++) s += s_dev[i];
            atomicAdd(&g_devacc, (unsigned long long)llrintf(s * S_DEV_F));
        }
        asm volatile("membar.gl;" ::: "memory");

        grid_barrier_fast((unsigned)ncta);            // sync B

        // ---- update theta regs; publish fp16 + warp max
        {
            float4 v = __ldcg(((const float4*)g_gradaccf) + tid);
            thf.x -= ETA * (v.x - prev.x);
            thf.y -= ETA * (v.y - prev.y);
            thf.z -= ETA * (v.z - prev.z);
            thf.w -= ETA * (v.w - prev.w);
            prev = v;
            __half2 h0 = __floats2half2_rn(thf.x, thf.y);
            __half2 h1 = __floats2half2_rn(thf.z, thf.w);
            uint2 u; u.x = *(unsigned*)&h0; u.y = *(unsigned*)&h1;
            ((uint2*)s_th2h)[tid] = u;
            float lm = fmaxf(fmaxf(fabsf(thf.x), fabsf(thf.y)),
                             fmaxf(fabsf(thf.z), fabsf(thf.w)));
#pragma unroll
            for (int o = 16; o; o >>= 1)
                lm = fmaxf(lm, __shfl_xor_sync(0xffffffffu, lm, o));
            if (lane == 0) s_max[w] = lm;
            if (cta == 0 && tid == 0) {
                long long dv = (long long)__ldcg(&g_devacc);
                float Lt = (float)(dv - devprev) * INV_SDEV * (1.0f / MDEVR);
                devprev = dv;
                if (1 + t < out_size) out[1 + t] = Lt;
                if (t >= 1) isum += Lt;
            }
        }
        __syncthreads();                              // sync C

        // ---- quantize theta int8 for the next step's dev pass
        {
            float gmax = s_max[0];
#pragma unroll
            for (int i = 1; i < NWARPS; i++) gmax = fmaxf(gmax, s_max[i]);
            sth = gmax * (1.0f / 127.0f);
            float tinv = (gmax > 0.0f) ? 127.0f / gmax : 0.0f;
            char4 tq;
            tq.x = quant8(thf.x, tinv); tq.y = quant8(thf.y, tinv);
            tq.z = quant8(thf.z, tinv); tq.w = quant8(thf.w, tinv);
            ((char4*)s_thq)[tid] = tq;
        }
        __syncthreads();                              // sync D
    }

    // ---- final dev eval at theta_T (s_thq/sth are current)
    {
        float dsum = 0.0f;
        int m = dfb;
        for (; m + 2 <= dfe; m += 2) dsum += dev_chunk_q<2>(m, lane, s_thq, sth, dyn);
        if (m < dfe)                 dsum += dev_chunk_q<1>(m, lane, s_thq, sth, dyn);
        if (lane == 0) s_dev[w] = dsum;
        __syncthreads();
        if (tid == 0) {
            float s = 0.0f;
#pragma unroll
            for (int i = 0; i < NWARPS; i++) s += s_dev[i];
            atomicAdd(&g_devacc, (unsigned long long)llrintf(s * S_DEV_F));
        }
        grid_barrier_full((unsigned)ncta);
        if (cta == 0 && tid == 0) {
            long long dv = (long long)g_devacc;
            float LT = (float)(dv - devprev) * INV_SDEV * (1.0f / MDEVR);
            if (out_size > 0) out[0] = (isum + LT) / (float)TST;
        }
    }
}

// ---------------------------------------------------------------------------
extern "C" void kernel_launch(void* const* d_in, const int* in_sizes, int n_in,
                              void* d_out, int out_size) {
    const float *theta = nullptr, *alphas = nullptr, *xn = nullptr,
                *yn = nullptr, *dxn = nullptr, *dyn = nullptr;
    for (int i = 0; i < n_in; i++) {
        switch (in_sizes[i]) {
            case DIMV:         theta  = (const float*)d_in[i]; break;
            case TST * NTR:    alphas = (const float*)d_in[i]; break;
            case NTR * DIMV:   xn     = (const float*)d_in[i]; break;
            case NTR:          yn     = (const float*)d_in[i]; break;
            case MDEVR * DIMV: dxn    = (const float*)d_in[i]; break;
            case MDEVR:        dyn    = (const float*)d_in[i]; break;
            default: break;
        }
    }
    float* out = (float*)d_out;

    int dev = 0;
    cudaGetDevice(&dev);
    int nsm = 0;
    cudaDeviceGetAttribute(&nsm, cudaDevAttrMultiProcessorCount, dev);
    int ncta = nsm;
    if (ncta < 1)   ncta = 148;
    if (ncta > 512) ncta = 512;

    size_t smem = (size_t)DIMV * 2            // s_th2h fp16
                + (size_t)DIMV                // s_thq int8
                + (size_t)NWARPS * DIMV * 2   // s_grad
                + 2 * NWARPS * sizeof(float); // s_dev + s_max  (~70.2 KB)
    cudaFuncSetAttribute(ak_all, cudaFuncAttributeMaxDynamicSharedMemorySize,
                         (int)smem);

    ak_all<<<ncta, NTHREADS, smem>>>(theta, xn, dxn, yn, dyn, alphas,
                                     out, out_size);
}

// round 14
// speedup vs baseline: 1.5215x; 1.2671x over previous
#include <cuda_runtime.h>
#include <cuda_fp16.h>
#include <math.h>

#define DIMV 2048
#define NTR  4096
#define MDEVR 8192
#define TST  500
#define ETA  0.1f
#define NTHREADS 512
#define NWARPS 16

#define S_DEV_F    4.294967296e9f     /* 2^32 */
#define INV_SDEV   2.3283064365e-10f  /* 2^-32 */

// Persistent device state (static allocation — no cudaMalloc anywhere).
// g_arrive is never reset: barriers leave it a multiple of gridDim.x.
__device__ float              g_gradaccf[DIMV];       // f32 running totals
__device__ unsigned long long g_devstep[TST + 1];     // per-step dev sums
__device__ unsigned           g_arrive;
__device__ __half       g_xn_h[(size_t)NTR * DIMV];      // 16.8 MB fp16 train
__device__ signed char  g_dxn_q[(size_t)MDEVR * DIMV];   // 16.8 MB int8 dev
__device__ float        g_sx[MDEVR];                     // per-row dev scales

__device__ __forceinline__ void grid_barrier_full(unsigned nb) {
    __syncthreads();
    if (threadIdx.x == 0) {
        __threadfence();
        unsigned old = atomicAdd(&g_arrive, 1u);
        unsigned target = (old / nb + 1u) * nb;
        while (*((volatile unsigned*)&g_arrive) < target) { }
        __threadfence();
    }
    __syncthreads();
}

__device__ __forceinline__ float dev_loss_elem(float z, float y) {
    return fmaxf(z, 0.0f) - y * z + log1pf(expf(-fabsf(z)));
}

__device__ __forceinline__ void dot8h(__half2* acc2, const uint4& u, const uint4& th) {
    const __half2* h = (const __half2*)&u;
    const __half2* t = (const __half2*)&th;
    acc2[0] = __hfma2(h[0], t[0], acc2[0]);
    acc2[1] = __hfma2(h[1], t[1], acc2[1]);
    acc2[2] = __hfma2(h[2], t[2], acc2[2]);
    acc2[3] = __hfma2(h[3], t[3], acc2[3]);
}

__device__ __forceinline__ void grad8h(__half2* gj, const uint4& u, __half2 ch2) {
    const __half2* h = (const __half2*)&u;
    gj[0] = __hfma2(ch2, h[0], gj[0]);
    gj[1] = __hfma2(ch2, h[1], gj[1]);
    gj[2] = __hfma2(ch2, h[2], gj[2]);
    gj[3] = __hfma2(ch2, h[3], gj[3]);
}

__device__ __forceinline__ float acc4_to_float(const __half2* a) {
    float2 f0 = __half22float2(a[0]);
    float2 f1 = __half22float2(a[1]);
    float2 f2 = __half22float2(a[2]);
    float2 f3 = __half22float2(a[3]);
    return (f0.x + f0.y) + (f1.x + f1.y) + (f2.x + f2.y) + (f3.x + f3.y);
}

// R contiguous train rows; theta fp16 in smem. z identical on all lanes.
template<int R>
__device__ __forceinline__ void train_chunk(
    int n0, int lane, int t, const __half* s_th, __half2* hacc,
    const float* __restrict__ yn, const float* __restrict__ alphas)
{
    const uint4* xp[R];
#pragma unroll
    for (int r = 0; r < R; r++)
        xp[r] = (const uint4*)(g_xn_h + (size_t)(n0 + r) * DIMV);
    const uint4* tp = (const uint4*)s_th;
    const __half2 hz = __float2half2_rn(0.0f);
    __half2 a[R][4];
#pragma unroll
    for (int r = 0; r < R; r++) { a[r][0]=hz; a[r][1]=hz; a[r][2]=hz; a[r][3]=hz; }
#pragma unroll
    for (int j = 0; j < 8; j++) {
        uint4 th = tp[j*32+lane];
#pragma unroll
        for (int r = 0; r < R; r++) {
            uint4 u = xp[r][j*32+lane];
            dot8h(a[r], u, th);
        }
    }
    float z[R];
#pragma unroll
    for (int r = 0; r < R; r++) z[r] = acc4_to_float(a[r]);
#pragma unroll
    for (int o = 16; o; o >>= 1) {
#pragma unroll
        for (int r = 0; r < R; r++)
            z[r] += __shfl_xor_sync(0xffffffffu, z[r], o);
    }
    __half2 ch[R];
#pragma unroll
    for (int r = 0; r < R; r++) {
        float s = 1.0f / (1.0f + expf(-z[r]));
        float c = alphas[(size_t)t * NTR + (n0 + r)] * (s - yn[n0 + r]);
        ch[r] = __float2half2_rn(c);
    }
#pragma unroll
    for (int j = 0; j < 8; j++) {
#pragma unroll
        for (int r = 0; r < R; r++) {
            uint4 u = xp[r][j*32+lane];         // L1 hits
            grad8h(hacc + j*4, u, ch[r]);
        }
    }
}

// R contiguous dev rows, int8: exact dp4a int32 dot; z = sx*sth*acc.
// Returns full loss sum, identical on all lanes.
template<int R>
__device__ __forceinline__ float dev_chunk_q(
    int m0, int lane, const signed char* s_thq, float sth,
    const float* __restrict__ dyn)
{
    const uint4* xp[R];
#pragma unroll
    for (int r = 0; r < R; r++)
        xp[r] = (const uint4*)(g_dxn_q + (size_t)(m0 + r) * DIMV);
    const uint4* tp = (const uint4*)s_thq;
    int acc[R];
#pragma unroll
    for (int r = 0; r < R; r++) acc[r] = 0;
#pragma unroll
    for (int j = 0; j < 4; j++) {                 // 4 uint4 = 64 int8/thread
        uint4 tq = tp[j*32+lane];
#pragma unroll
        for (int r = 0; r < R; r++) {
            uint4 u = xp[r][j*32+lane];
            acc[r] = __dp4a((int)u.x, (int)tq.x, acc[r]);
            acc[r] = __dp4a((int)u.y, (int)tq.y, acc[r]);
            acc[r] = __dp4a((int)u.z, (int)tq.z, acc[r]);
            acc[r] = __dp4a((int)u.w, (int)tq.w, acc[r]);
        }
    }
#pragma unroll
    for (int o = 16; o; o >>= 1) {
#pragma unroll
        for (int r = 0; r < R; r++)
            acc[r] += __shfl_xor_sync(0xffffffffu, acc[r], o);
    }
    float s = 0.0f;
#pragma unroll
    for (int r = 0; r < R; r++) {
        float z = g_sx[m0 + r] * sth * (float)acc[r];
        s += dev_loss_elem(z, dyn[m0 + r]);
    }
    return s;
}

__device__ __forceinline__ signed char quant8(float v, float inv) {
    float q = fminf(fmaxf(v * inv, -127.0f), 127.0f);
    return (signed char)__float2int_rn(q);
}

// ---------------------------------------------------------------------------
__global__ void __launch_bounds__(NTHREADS, 1)
ak_all(const float* __restrict__ theta0,
       const float* __restrict__ xn,  const float* __restrict__ dxn,
       const float* __restrict__ yn,  const float* __restrict__ dyn,
       const float* __restrict__ alphas,
       float* __restrict__ out, int out_size) {
    extern __shared__ char smc[];
    __half*      s_th2h = (__half*)smc;                          // 4 KB fp16
    signed char* s_thq  = (signed char*)(smc + DIMV * 2);        // 2 KB int8
    __half*      s_grad = (__half*)(smc + DIMV * 2 + DIMV);      // 64 KB
    float*       s_dev  = (float*)(smc + DIMV * 2 + DIMV
                                   + (size_t)NWARPS * DIMV * 2); // 16 floats
    float*       s_maxA = s_dev + NWARPS;                        // 16 floats
    float*       s_maxB = s_maxA + NWARPS;                       // 16 floats

    const int tid  = threadIdx.x;
    const int lane = tid & 31;
    const int w    = tid >> 5;
    const int cta  = blockIdx.x;
    const int ncta = gridDim.x;

    // ---------------- phase 0: convert train fp16 + quantize dev int8 ----
    {
        const size_t stride = (size_t)ncta * NTHREADS;
        const size_t gid    = (size_t)cta * NTHREADS + tid;
        const size_t n4 = (size_t)NTR * DIMV / 4;
        const float4* s0 = (const float4*)xn;
        __half2* d0 = (__half2*)g_xn_h;
        for (size_t i = gid; i < n4; i += stride) {
            float4 v = s0[i];
            d0[2*i+0] = __floats2half2_rn(v.x, v.y);
            d0[2*i+1] = __floats2half2_rn(v.z, v.w);
        }
        const int gwp = cta * NWARPS + w;
        const int nwp = ncta * NWARPS;
        for (int row = gwp; row < MDEVR; row += nwp) {
            const float4* xr = (const float4*)(dxn + (size_t)row * DIMV);
            float mx = 0.0f;
            for (int i = lane; i < DIMV / 4; i += 32) {
                float4 v = xr[i];
                mx = fmaxf(mx, fmaxf(fmaxf(fabsf(v.x), fabsf(v.y)),
                                     fmaxf(fabsf(v.z), fabsf(v.w))));
            }
#pragma unroll
            for (int o = 16; o; o >>= 1)
                mx = fmaxf(mx, __shfl_xor_sync(0xffffffffu, mx, o));
            float inv = (mx > 0.0f) ? 127.0f / mx : 0.0f;
            if (lane == 0) g_sx[row] = (mx > 0.0f) ? mx * (1.0f / 127.0f) : 0.0f;
            char4* dq = (char4*)(g_dxn_q + (size_t)row * DIMV);
            for (int i = lane; i < DIMV / 4; i += 32) {
                float4 v = xr[i];
                char4 q;
                q.x = quant8(v.x, inv); q.y = quant8(v.y, inv);
                q.z = quant8(v.z, inv); q.w = quant8(v.w, inv);
                dq[i] = q;
            }
        }
        if (gid < DIMV)    g_gradaccf[gid] = 0.0f;
        if (gid < TST + 1) g_devstep[gid] = 0ull;
        for (size_t j = TST + 1 + gid; j < (size_t)out_size; j += stride)
            out[j] = 0.0f;
    }
    // theta fp32 -> registers (dims 4*tid..+3); publish fp16 + maxes
    float4 thf = ((const float4*)theta0)[tid];
    {
        __half2 h0 = __floats2half2_rn(thf.x, thf.y);
        __half2 h1 = __floats2half2_rn(thf.z, thf.w);
        uint2 u; u.x = *(unsigned*)&h0; u.y = *(unsigned*)&h1;
        ((uint2*)s_th2h)[tid] = u;
        float lm = fmaxf(fmaxf(fabsf(thf.x), fabsf(thf.y)),
                         fmaxf(fabsf(thf.z), fabsf(thf.w)));
#pragma unroll
        for (int o = 16; o; o >>= 1)
            lm = fmaxf(lm, __shfl_xor_sync(0xffffffffu, lm, o));
        if (lane == 0) { s_maxA[w] = lm; s_maxB[w] = lm; }
    }
    grid_barrier_full((unsigned)ncta);
    float sth;
    {   // initial exact int8 theta (identical in every CTA)
        float gmax = s_maxA[0];
#pragma unroll
        for (int i = 1; i < NWARPS; i++) gmax = fmaxf(gmax, s_maxA[i]);
        gmax *= 1.25f;                       // uniform margin (lazy-scale law)
        sth = gmax * (1.0f / 127.0f);
        float tinv = (gmax > 0.0f) ? 127.0f / gmax : 0.0f;
        char4 tq;
        tq.x = quant8(thf.x, tinv); tq.y = quant8(thf.y, tinv);
        tq.z = quant8(thf.z, tinv); tq.w = quant8(thf.w, tinv);
        ((char4*)s_thq)[tid] = tq;
    }
    __syncthreads();

    // CTA row ranges
    const int rb = (int)(((long long)cta * NTR) / ncta);
    const int re = (int)(((long long)(cta + 1) * NTR) / ncta);
    const int mb = (int)(((long long)cta * MDEVR) / ncta);
    const int me = (int)(((long long)(cta + 1) * MDEVR) / ncta);
    const int Tr = re - rb, Dr = me - mb;
    // per-warp exact splits (train and dev separately; dev hides barrier)
    const int twb = rb + (int)(((long long)Tr * w) / NWARPS);
    const int twe = rb + (int)(((long long)Tr * (w + 1)) / NWARPS);
    const int dwb = mb + (int)(((long long)Dr * w) / NWARPS);
    const int dwe = mb + (int)(((long long)Dr * (w + 1)) / NWARPS);

    float4 prev = make_float4(0.0f, 0.0f, 0.0f, 0.0f);
    const __half2 hz = __float2half2_rn(0.0f);
    unsigned my_arr = 0;   // tid0: my arrival ticket

    for (int t = 0; t < TST; ++t) {
        // ---- train rows with theta_t
        __half2 hacc[32];
#pragma unroll
        for (int j = 0; j < 32; j++) hacc[j] = hz;
        {
            int n = twb;
            for (; n + 2 <= twe; n += 2) train_chunk<2>(n, lane, t, s_th2h, hacc, yn, alphas);
            if (n < twe)                 train_chunk<1>(n, lane, t, s_th2h, hacc, yn, alphas);
        }
        {
            uint4* gp4 = (uint4*)(s_grad + (size_t)w * DIMV);
#pragma unroll
            for (int j = 0; j < 8; j++) {
                uint4 u;
                ((__half2*)&u)[0] = hacc[j*4+0];
                ((__half2*)&u)[1] = hacc[j*4+1];
                ((__half2*)&u)[2] = hacc[j*4+2];
                ((__half2*)&u)[3] = hacc[j*4+3];
                gp4[j*32+lane] = u;
            }
        }
        __syncthreads();                              // A

        // ---- CTA reduce + f32 REDs, release, ARRIVE (no wait yet)
        {
            const __half2* sg2 = (const __half2*)s_grad;
#pragma unroll
            for (int i = 0; i < 2; i++) {
                int idx = tid + i * NTHREADS;
                float2 s = make_float2(0.0f, 0.0f);
#pragma unroll
                for (int ww = 0; ww < NWARPS; ww++) {
                    float2 f = __half22float2(sg2[ww * (DIMV/2) + idx]);
                    s.x += f.x; s.y += f.y;
                }
                atomicAdd(&g_gradaccf[2*idx+0], s.x);
                atomicAdd(&g_gradaccf[2*idx+1], s.y);
            }
        }
        asm volatile("membar.gl;" ::: "memory");
        __syncthreads();                              // B (REDs released)
        if (tid == 0) my_arr = atomicAdd(&g_arrive, 1u);

        // ---- dev pass with theta_t — HIDES the barrier release latency
        float dsum = 0.0f;
        {
            int m = dwb;
            for (; m + 2 <= dwe; m += 2) dsum += dev_chunk_q<2>(m, lane, s_thq, sth, dyn);
            if (m < dwe)                 dsum += dev_chunk_q<1>(m, lane, s_thq, sth, dyn);
        }
        if (lane == 0) s_dev[w] = dsum;
        __syncthreads();                              // C
        if (tid == 0) {
            float s = 0.0f;
#pragma unroll
            for (int i = 0; i < NWARPS; i++) s += s_dev[i];
            atomicAdd(&g_devstep[t], (unsigned long long)llrintf(s * S_DEV_F));
            // now wait for the step-t gradient barrier (usually already open)
            unsigned target = (my_arr / (unsigned)ncta + 1u) * (unsigned)ncta;
            while (*((volatile unsigned*)&g_arrive) < target) { }
        }
        __syncthreads();                              // D

        // ---- update theta regs; publish fp16 + int8 (lazy scale) + maxes
        {
            const float* s_rd = (t & 1) ? s_maxB : s_maxA;  // prev step's maxes
            float*       s_wr = (t & 1) ? s_maxA : s_maxB;
            float gmax = s_rd[0];
#pragma unroll
            for (int i = 1; i < NWARPS; i++) gmax = fmaxf(gmax, s_rd[i]);
            gmax *= 1.25f;
            sth = gmax * (1.0f / 127.0f);
            float tinv = (gmax > 0.0f) ? 127.0f / gmax : 0.0f;

            float4 v = __ldcg(((const float4*)g_gradaccf) + tid);
            thf.x -= ETA * (v.x - prev.x);
            thf.y -= ETA * (v.y - prev.y);
            thf.z -= ETA * (v.z - prev.z);
            thf.w -= ETA * (v.w - prev.w);
            prev = v;
            __half2 h0 = __floats2half2_rn(thf.x, thf.y);
            __half2 h1 = __floats2half2_rn(thf.z, thf.w);
            uint2 u; u.x = *(unsigned*)&h0; u.y = *(unsigned*)&h1;
            ((uint2*)s_th2h)[tid] = u;
            char4 tq;
            tq.x = quant8(thf.x, tinv); tq.y = quant8(thf.y, tinv);
            tq.z = quant8(thf.z, tinv); tq.w = quant8(thf.w, tinv);
            ((char4*)s_thq)[tid] = tq;
            float lm = fmaxf(fmaxf(fabsf(thf.x), fabsf(thf.y)),
                             fmaxf(fabsf(thf.z), fabsf(thf.w)));
#pragma unroll
            for (int o = 16; o; o >>= 1)
                lm = fmaxf(lm, __shfl_xor_sync(0xffffffffu, lm, o));
            if (lane == 0) s_wr[w] = lm;
        }
        __syncthreads();                              // E
    }

    // ---- final dev eval at theta_T (s_thq/sth current), then publish all
    {
        float dsum = 0.0f;
        int m = dwb;
        for (; m + 2 <= dwe; m += 2) dsum += dev_chunk_q<2>(m, lane, s_thq, sth, dyn);
        if (m < dwe)                 dsum += dev_chunk_q<1>(m, lane, s_thq, sth, dyn);
        if (lane == 0) s_dev[w] = dsum;
        __syncthreads();
        if (tid == 0) {
            float s = 0.0f;
#pragma unroll
            for (int i = 0; i < NWARPS; i++) s += s_dev[i];
            atomicAdd(&g_devstep[TST], (unsigned long long)llrintf(s * S_DEV_F));
        }
        grid_barrier_full((unsigned)ncta);
        if (cta == 0) {
            for (int ts = tid; ts < TST; ts += NTHREADS) {
                float L = (float)((long long)g_devstep[ts]) * INV_SDEV * (1.0f / MDEVR);
                if (1 + ts < out_size) out[1 + ts] = L;
            }
            if (tid == 0) {
                float isum = 0.0f;
                for (int ts = 1; ts <= TST; ts++)
                    isum += (float)((long long)g_devstep[ts]) * INV_SDEV * (1.0f / MDEVR);
                if (out_size > 0) out[0] = isum / (float)TST;
            }
        }
    }
}

// ---------------------------------------------------------------------------
extern "C" void kernel_launch(void* const* d_in, const int* in_sizes, int n_in,
                              void* d_out, int out_size) {
    const float *theta = nullptr, *alphas = nullptr, *xn = nullptr,
                *yn = nullptr, *dxn = nullptr, *dyn = nullptr;
    for (int i = 0; i < n_in; i++) {
        switch (in_sizes[i]) {
            case DIMV:         theta  = (const float*)d_in[i]; break;
            case TST * NTR:    alphas = (const float*)d_in[i]; break;
            case NTR * DIMV:   xn     = (const float*)d_in[i]; break;
            case NTR:          yn     = (const float*)d_in[i]; break;
            case MDEVR * DIMV: dxn    = (const float*)d_in[i]; break;
            case MDEVR:        dyn    = (const float*)d_in[i]; break;
            default: break;
        }
    }
    float* out = (float*)d_out;

    int dev = 0;
    cudaGetDevice(&dev);
    int nsm = 0;
    cudaDeviceGetAttribute(&nsm, cudaDevAttrMultiProcessorCount, dev);
    int ncta = nsm;
    if (ncta < 1)   ncta = 148;
    if (ncta > 512) ncta = 512;

    size_t smem = (size_t)DIMV * 2            // s_th2h fp16
                + (size_t)DIMV                // s_thq int8
                + (size_t)NWARPS * DIMV * 2   // s_grad
                + 3 * NWARPS * sizeof(float); // s_dev + s_maxA + s_maxB
    cudaFuncSetAttribute(ak_all, cudaFuncAttributeMaxDynamicSharedMemorySize,
                         (int)smem);

    ak_all<<<ncta, NTHREADS, smem>>>(theta, xn, dxn, yn, dyn, alphas,
                                     out, out_size);
}